// round 12
// baseline (speedup 1.0000x reference)
#include <cuda_runtime.h>

#define NB 2
#define NH 16
#define NM 2048
#define ND 1024
#define NDH 64
#define NS 2048
#define NK 256

// Scratch (device globals; no allocations allowed)
__device__ float g_q[NB * NM * ND];
__device__ float g_kt[NB * ND * NM];               // k transposed [b][d][m]
__device__ float g_vt[NB * ND * NM];               // v transposed [b][d][m]
__device__ float g_o[NB * NM * ND];
__device__ float g_kp[NB * NK * ND];               // k proj [b][k][d]
__device__ float g_vp[NB * NK * ND];               // v proj [b][k][d]
__device__ float g_sb[NB * NH * NM * NK];          // bias scores [B,H,M,K]
__device__ float g_pp[16 * NK * ND];               // proj split-K partials
__device__ __align__(16) unsigned short g_ek16[NK * NS];   // Ek as fp16

// ---------------- packed f32x2 helpers (attn2) ----------------
static __device__ __forceinline__ unsigned long long splat2(float x) {
    unsigned long long r;
    asm("mov.b64 %0, {%1, %1};" : "=l"(r) : "f"(x));
    return r;
}
static __device__ __forceinline__ void fma2(unsigned long long &c,
                                            unsigned long long a,
                                            unsigned long long b) {
    asm("fma.rn.f32x2 %0, %1, %2, %0;" : "+l"(c) : "l"(a), "l"(b));
}
static __device__ __forceinline__ float2 unpk(unsigned long long v) {
    float2 f;
    asm("mov.b64 {%0, %1}, %2;" : "=f"(f.x), "=f"(f.y) : "l"(v));
    return f;
}

// ---------------- fp16 mma helpers ----------------
static __device__ __forceinline__ unsigned s2u(const void* p) {
    unsigned a;
    asm("{ .reg .u64 t; cvta.to.shared.u64 t, %1; cvt.u32.u64 %0, t; }" : "=r"(a) : "l"(p));
    return a;
}
static __device__ __forceinline__ unsigned pack2(float lo, float hi) {
    unsigned r;
    asm("cvt.rn.f16x2.f32 %0, %1, %2;" : "=r"(r) : "f"(hi), "f"(lo));
    return r;
}
static __device__ __forceinline__ void ldm4(unsigned* r, unsigned a) {
    asm volatile("ldmatrix.sync.aligned.m8n8.x4.shared.b16 {%0,%1,%2,%3}, [%4];"
                 : "=r"(r[0]), "=r"(r[1]), "=r"(r[2]), "=r"(r[3]) : "r"(a));
}
static __device__ __forceinline__ void mma16(float* c, const unsigned* a,
                                             unsigned b0, unsigned b1) {
    asm volatile(
        "mma.sync.aligned.m16n8k16.row.col.f32.f16.f16.f32 "
        "{%0,%1,%2,%3}, {%4,%5,%6,%7}, {%8,%9}, {%0,%1,%2,%3};"
        : "+f"(c[0]), "+f"(c[1]), "+f"(c[2]), "+f"(c[3])
        : "r"(a[0]), "r"(a[1]), "r"(a[2]), "r"(a[3]), "r"(b0), "r"(b1));
}
static __device__ __forceinline__ void cpa16(unsigned dst, const void* src) {
    asm volatile("cp.async.cg.shared.global [%0], [%1], 16;" :: "r"(dst), "l"(src) : "memory");
}

#define BM 128
#define BN 128
#define BK 64
#define BKH 72                         // padded half stride
#define TILEH (128 * BKH)              // 9216 halves per tile
#define SM16 (4 * TILEH * 2)           // 73728 bytes

// ---------------------------------------------------------------------------
// tc16_body: C tile [128x128] = A @ B^T (+bias) via fp16 m16n8k16, fp32 accum.
// KdS = row stride of A and B; Kd = K-length to accumulate (Kd <= KdS slice).
// If Ct != nullptr: write transposed Ct[(n0+c)*CtStride + m_local].
// ---------------------------------------------------------------------------
static __device__ __forceinline__ void tc16_body(
    const float* __restrict__ A, const float* __restrict__ Bm,
    const float* __restrict__ bias, float* __restrict__ C, int Nld,
    int Kd, int KdS, int bx, int by, float* __restrict__ Ct, int CtStride)
{
    extern __shared__ unsigned short smh[];
    const unsigned sbase = s2u(smh);
    const int tid = threadIdx.x, lane = tid & 31, wid = tid >> 5;
    const size_t m0 = (size_t)bx * BM;
    const int n0 = by * BN;

    const int ldr = tid >> 3, ldc = (tid & 7) * 8;
    const float* Ag = A + (m0 + ldr) * (size_t)KdS + ldc;
    const float* Bg = Bm + (size_t)(n0 + ldr) * KdS + ldc;
    const unsigned sOff = (unsigned)(ldr * BKH + ldc) * 2;

    auto ld = [&](int k0, int buf) {
        unsigned ab = sbase + (unsigned)(buf * 2 * TILEH) * 2 + sOff;
        unsigned bb = ab + (unsigned)TILEH * 2;
#pragma unroll
        for (int j = 0; j < 4; j++) {
            const size_t ro = (size_t)(j * 32) * KdS;
            const unsigned so = (unsigned)(j * 32 * BKH) * 2;
#pragma unroll
            for (int h = 0; h < 2; h++) {
                float4 v = *(const float4*)(Ag + ro + k0 + h * 4);
                unsigned u0 = pack2(v.x, v.y), u1 = pack2(v.z, v.w);
                asm volatile("st.shared.v2.b32 [%0], {%1,%2};"
                             :: "r"(ab + so + h * 8), "r"(u0), "r"(u1) : "memory");
                float4 t = *(const float4*)(Bg + ro + k0 + h * 4);
                unsigned w0 = pack2(t.x, t.y), w1 = pack2(t.z, t.w);
                asm volatile("st.shared.v2.b32 [%0], {%1,%2};"
                             :: "r"(bb + so + h * 8), "r"(w0), "r"(w1) : "memory");
            }
        }
    };

    const int wm = (wid >> 2) * 64, wn = (wid & 3) * 32;
    const int gr = lane >> 2, gc = lane & 3;
    const unsigned frow = (unsigned)(lane & 15), fcol = (unsigned)((lane >> 4) * 8);

    float acc[4][4][4];
#pragma unroll
    for (int mt = 0; mt < 4; mt++)
#pragma unroll
        for (int nt = 0; nt < 4; nt++)
#pragma unroll
            for (int e = 0; e < 4; e++) acc[mt][nt][e] = 0.f;

    ld(0, 0);
    __syncthreads();

    const int nk = Kd / BK;
    for (int i = 0; i < nk; i++) {
        if (i + 1 < nk) ld((i + 1) * BK, (i + 1) & 1);
        const unsigned tb = sbase + (unsigned)((i & 1) * 2 * TILEH) * 2;
#pragma unroll
        for (int k16 = 0; k16 < BK; k16 += 16) {
            unsigned af[4][4], bf[4][2];
#pragma unroll
            for (int mt = 0; mt < 4; mt++) {
                unsigned a = tb + ((unsigned)(wm + mt * 16 + frow) * BKH + k16 + fcol) * 2;
                ldm4(af[mt], a);
            }
#pragma unroll
            for (int np = 0; np < 2; np++) {
                unsigned a = tb + (unsigned)TILEH * 2 +
                             ((unsigned)(wn + np * 16 + frow) * BKH + k16 + fcol) * 2;
                unsigned r[4];
                ldm4(r, a);
                bf[2 * np + 0][0] = r[0]; bf[2 * np + 1][0] = r[1];
                bf[2 * np + 0][1] = r[2]; bf[2 * np + 1][1] = r[3];
            }
#pragma unroll
            for (int mt = 0; mt < 4; mt++)
#pragma unroll
                for (int nt = 0; nt < 4; nt++)
                    mma16(acc[mt][nt], af[mt], bf[nt][0], bf[nt][1]);
        }
        __syncthreads();
    }

    if (!Ct) {
#pragma unroll
        for (int mt = 0; mt < 4; mt++) {
            const size_t r = m0 + wm + mt * 16 + gr;
            float* cp0 = C + r * (size_t)Nld;
            float* cp1 = C + (r + 8) * (size_t)Nld;
#pragma unroll
            for (int nt = 0; nt < 4; nt++) {
                const int c = n0 + wn + nt * 8 + 2 * gc;
                float b0 = bias ? bias[c] : 0.f;
                float b1 = bias ? bias[c + 1] : 0.f;
                *(float2*)(cp0 + c) = make_float2(acc[mt][nt][0] + b0, acc[mt][nt][1] + b1);
                *(float2*)(cp1 + c) = make_float2(acc[mt][nt][2] + b0, acc[mt][nt][3] + b1);
            }
        }
    } else {
        float* st32 = (float*)smh;   // [128][132]
        __syncthreads();
#pragma unroll
        for (int mt = 0; mt < 4; mt++) {
            const int r0 = wm + mt * 16 + gr;
#pragma unroll
            for (int nt = 0; nt < 4; nt++) {
                const int c = wn + nt * 8 + 2 * gc;
                float b0 = bias ? bias[n0 + c] : 0.f;
                float b1 = bias ? bias[n0 + c + 1] : 0.f;
                st32[r0 * 132 + c] = acc[mt][nt][0] + b0;
                st32[r0 * 132 + c + 1] = acc[mt][nt][1] + b1;
                st32[(r0 + 8) * 132 + c] = acc[mt][nt][2] + b0;
                st32[(r0 + 8) * 132 + c + 1] = acc[mt][nt][3] + b1;
            }
        }
        __syncthreads();
#pragma unroll
        for (int i = 0; i < 16; i++) {
            const int c = wid * 16 + i;
            float4 o;
            o.x = st32[(lane * 4 + 0) * 132 + c];
            o.y = st32[(lane * 4 + 1) * 132 + c];
            o.z = st32[(lane * 4 + 2) * 132 + c];
            o.w = st32[(lane * 4 + 3) * 132 + c];
            *(float4*)(Ct + (size_t)(n0 + c) * CtStride + lane * 4) = o;
        }
        __syncthreads();
    }
}

__global__ __launch_bounds__(256) void k_qkv16(const float* __restrict__ z,
                                               const float* __restrict__ W0,
                                               const float* __restrict__ W1,
                                               const float* __restrict__ W2,
                                               const float* __restrict__ b0,
                                               const float* __restrict__ b1,
                                               const float* __restrict__ b2)
{
    const int zz = blockIdx.z;
    const float* W = (zz == 0) ? W0 : (zz == 1) ? W1 : W2;
    const float* bb = (zz == 0) ? b0 : (zz == 1) ? b1 : b2;
    if (zz == 0) {
        tc16_body(z, W, bb, g_q, ND, ND, ND, blockIdx.x, blockIdx.y, nullptr, 0);
    } else {
        const int b = blockIdx.x >> 4;
        const int mloc = (blockIdx.x & 15) * BM;
        float* base = ((zz == 1) ? g_kt : g_vt) + (size_t)b * ND * NM + mloc;
        tc16_body(z, W, bb, nullptr, 0, ND, ND, blockIdx.x, blockIdx.y, base, NM);
    }
}

// proj split-K x4: z = gemm*4 + split; gemm 0,1 = Ek@kt[b]^T, 2,3 = Ev@vt[b]^T
__global__ __launch_bounds__(256) void k_proj16s(const float* __restrict__ Ek,
                                                 const float* __restrict__ Ev)
{
    const int bz = blockIdx.z;
    const int zz = bz >> 2, sp = bz & 3;
    const int koff = sp * 512;
    const float* A = ((zz < 2) ? Ek : Ev) + koff;
    const float* Bm = (((zz < 2) ? g_kt : g_vt) + (size_t)(zz & 1) * ND * NM) + koff;
    float* C = g_pp + (size_t)bz * (NK * ND);
    tc16_body(A, Bm, nullptr, C, ND, 512, NM, blockIdx.x, blockIdx.y, nullptr, 0);
}

__global__ __launch_bounds__(256) void k_projred()
{
    const size_t i = (size_t)blockIdx.x * 256 + threadIdx.x;   // over 4*NK*ND
    const int zz = (int)(i / (NK * ND));
    const size_t r = i - (size_t)zz * (NK * ND);
    const size_t base = (size_t)(zz * 4) * (NK * ND) + r;
    float s = g_pp[base] + g_pp[base + (size_t)NK * ND] +
              g_pp[base + 2 * (size_t)NK * ND] + g_pp[base + 3 * (size_t)NK * ND];
    float* dst = (zz < 2) ? g_kp : g_vp;
    dst[(size_t)(zz & 1) * NK * ND + r] = s;
}

__global__ __launch_bounds__(256) void k_out16(const float* __restrict__ Wo,
                                               const float* __restrict__ bo,
                                               float* __restrict__ out)
{
    tc16_body(g_o, Wo, bo, out, ND, ND, ND, blockIdx.x, blockIdx.y, nullptr, 0);
}

// ---------------------------------------------------------------------------
// k_cvt: Ek fp32 -> fp16 table (once)
// ---------------------------------------------------------------------------
__global__ __launch_bounds__(256) void k_cvt(const float* __restrict__ Ek)
{
    const int i = blockIdx.x * 256 + threadIdx.x;   // over NK*NS/2
    float2 v = *(const float2*)(Ek + 2 * (size_t)i);
    *(unsigned*)(g_ek16 + 2 * (size_t)i) = pack2(v.x, v.y);
}

// ---------------------------------------------------------------------------
// k_bias256 v3: 512 threads (16 warps), warp tile 32x64, CTA tile 128x256.
// acc = 64 regs/thread -> ~115 regs total -> full-RF single CTA = 16 warps/SM.
// B (Ek16) via cp.async; A (geom+cont) LDG-staged across the MMA section.
// ---------------------------------------------------------------------------
#define BK2 32
#define BKH2 40                        // padded half stride (80 B)
#define A2T (128 * BKH2)               // 5120 halves per A buffer
#define B2T (256 * BKH2)               // 10240 halves per B buffer
#define SMP2 ((2 * A2T + 2 * B2T) * 2) // 61440 bytes

__global__ __launch_bounds__(512) void k_bias256(const float* __restrict__ geom,
                                                 const float* __restrict__ cont,
                                                 float* __restrict__ sb)
{
    extern __shared__ unsigned short smh[];
    const unsigned sbase = s2u(smh);
    const unsigned bbase = sbase + (unsigned)(2 * A2T) * 2;
    const int tid = threadIdx.x, lane = tid & 31, wid = tid >> 5;
    const size_t m0 = (size_t)blockIdx.x * BM;      // row in flattened [B*H*M]

    // A loader: row = tid>>2 (0..127), col = (tid&3)*8 floats (2 x float4)
    const int ar = tid >> 2, ac = (tid & 3) * 8;
    const float* Ag = geom + (m0 + ar) * (size_t)NS + ac;
    const float* Cg = cont + (m0 + ar) * (size_t)NS + ac;
    const unsigned aoff = (unsigned)(ar * BKH2 + ac) * 2;
    // B loader: row = tid>>1 (0..255), col = (tid&1)*16 halves (2 x cp.async16)
    const int br = tid >> 1, bc = (tid & 1) * 16;
    const unsigned short* Bg = g_ek16 + (size_t)br * NS + bc;
    const unsigned boff = (unsigned)(br * BKH2 + bc) * 2;

    float4 sg[2], sc[2];   // A staging (16 regs)

    auto ldgA = [&](int k0) {
        sg[0] = *(const float4*)(Ag + k0);
        sg[1] = *(const float4*)(Ag + k0 + 4);
        sc[0] = *(const float4*)(Cg + k0);
        sc[1] = *(const float4*)(Cg + k0 + 4);
    };
    auto stsA = [&](int buf) {
        unsigned ab = sbase + (unsigned)(buf * A2T) * 2 + aoff;
        unsigned p0 = pack2(sg[0].x + sc[0].x, sg[0].y + sc[0].y);
        unsigned p1 = pack2(sg[0].z + sc[0].z, sg[0].w + sc[0].w);
        unsigned p2 = pack2(sg[1].x + sc[1].x, sg[1].y + sc[1].y);
        unsigned p3 = pack2(sg[1].z + sc[1].z, sg[1].w + sc[1].w);
        asm volatile("st.shared.v4.b32 [%0], {%1,%2,%3,%4};"
                     :: "r"(ab), "r"(p0), "r"(p1), "r"(p2), "r"(p3) : "memory");
    };
    auto cpB = [&](int k0, int buf) {
        unsigned bb = bbase + (unsigned)(buf * B2T) * 2 + boff;
        cpa16(bb, Bg + k0);
        cpa16(bb + 16, Bg + k0 + 8);
    };

    const int wm = (wid >> 2) * 32, wn = (wid & 3) * 64;
    const int gr = lane >> 2, gc = lane & 3;
    const unsigned frow = (unsigned)(lane & 15), fcol = (unsigned)((lane >> 4) * 8);

    float acc[2][8][4];
#pragma unroll
    for (int mt = 0; mt < 2; mt++)
#pragma unroll
        for (int nt = 0; nt < 8; nt++)
#pragma unroll
            for (int e = 0; e < 4; e++) acc[mt][nt][e] = 0.f;

    // prologue
    cpB(0, 0);
    asm volatile("cp.async.commit_group;" ::: "memory");
    ldgA(0);
    stsA(0);
    asm volatile("cp.async.wait_group 0;" ::: "memory");
    __syncthreads();

    const int nk = NS / BK2;   // 64
    for (int i = 0; i < nk; i++) {
        if (i + 1 < nk) {
            ldgA((i + 1) * BK2);                       // LDGs in flight over MMA
            cpB((i + 1) * BK2, (i + 1) & 1);
            asm volatile("cp.async.commit_group;" ::: "memory");
        }
        const unsigned ta = sbase + (unsigned)((i & 1) * A2T) * 2;
        const unsigned tb = bbase + (unsigned)((i & 1) * B2T) * 2;
#pragma unroll
        for (int k16 = 0; k16 < BK2; k16 += 16) {
            unsigned af[2][4], bf[8][2];
#pragma unroll
            for (int mt = 0; mt < 2; mt++) {
                unsigned a = ta + ((unsigned)(wm + mt * 16 + frow) * BKH2 + k16 + fcol) * 2;
                ldm4(af[mt], a);
            }
#pragma unroll
            for (int np = 0; np < 4; np++) {
                unsigned a = tb + ((unsigned)(wn + np * 16 + frow) * BKH2 + k16 + fcol) * 2;
                unsigned r[4];
                ldm4(r, a);
                bf[2 * np + 0][0] = r[0]; bf[2 * np + 1][0] = r[1];
                bf[2 * np + 0][1] = r[2]; bf[2 * np + 1][1] = r[3];
            }
#pragma unroll
            for (int mt = 0; mt < 2; mt++)
#pragma unroll
                for (int nt = 0; nt < 8; nt++)
                    mma16(acc[mt][nt], af[mt], bf[nt][0], bf[nt][1]);
        }
        if (i + 1 < nk) {
            stsA((i + 1) & 1);                         // consume staged LDGs
            asm volatile("cp.async.wait_group 0;" ::: "memory");
        }
        __syncthreads();
    }

#pragma unroll
    for (int mt = 0; mt < 2; mt++) {
        const size_t r = m0 + wm + mt * 16 + gr;
        float* cp0 = sb + r * (size_t)NK;
        float* cp1 = sb + (r + 8) * (size_t)NK;
#pragma unroll
        for (int nt = 0; nt < 8; nt++) {
            const int c = wn + nt * 8 + 2 * gc;
            *(float2*)(cp0 + c) = make_float2(acc[mt][nt][0], acc[mt][nt][1]);
            *(float2*)(cp1 + c) = make_float2(acc[mt][nt][2], acc[mt][nt][3]);
        }
    }
}

// ---------------------------------------------------------------------------
// Fused attention per (b, h, 64-row m tile)  (R7 version):
//   scores[64,256] = g_sb + (q/8)[64,64] @ kproj^T ; softmax; attn @ vproj
// ---------------------------------------------------------------------------
#define AST 72
#define BST 264
#define ATST 264
#define SMF_FLOATS (64 * ATST + 16 * AST)   // 18048 floats = 72192 B

__global__ __launch_bounds__(256) void attn2()
{
    extern __shared__ float sm[];
    float* As = sm;                 // [16][AST]
    float* Bs = sm + 16 * AST;      // [16][BST]
    const int m0 = blockIdx.x * 64;
    const int h = blockIdx.y, b = blockIdx.z;
    const int tid = threadIdx.x;
    const int tr = tid >> 5, tc = tid & 31;
    const int lrow = tid >> 2, lcg = (tid & 3) << 2;

    unsigned long long acc[4][8];
#pragma unroll
    for (int p = 0; p < 4; p++)
#pragma unroll
        for (int j = 0; j < 8; j++) acc[p][j] = 0ull;

    const float* qp = g_q + ((size_t)b * NM + m0) * ND + h * NDH;
    const float* kp = g_kp + ((size_t)b * NK + tid) * ND + h * NDH;
    for (int d0 = 0; d0 < NDH; d0 += 16) {
        const float* ep = kp + d0;
        float4 e0 = *(const float4*)(ep + 0);
        float4 e1 = *(const float4*)(ep + 4);
        float4 e2 = *(const float4*)(ep + 8);
        float4 e3 = *(const float4*)(ep + 12);
        Bs[0 * BST + tid] = e0.x;  Bs[1 * BST + tid] = e0.y;
        Bs[2 * BST + tid] = e0.z;  Bs[3 * BST + tid] = e0.w;
        Bs[4 * BST + tid] = e1.x;  Bs[5 * BST + tid] = e1.y;
        Bs[6 * BST + tid] = e1.z;  Bs[7 * BST + tid] = e1.w;
        Bs[8 * BST + tid] = e2.x;  Bs[9 * BST + tid] = e2.y;
        Bs[10 * BST + tid] = e2.z; Bs[11 * BST + tid] = e2.w;
        Bs[12 * BST + tid] = e3.x; Bs[13 * BST + tid] = e3.y;
        Bs[14 * BST + tid] = e3.z; Bs[15 * BST + tid] = e3.w;

        float4 qv = *(const float4*)(qp + (size_t)lrow * ND + d0 + lcg);
        As[(lcg + 0) * AST + lrow] = qv.x * 0.125f;
        As[(lcg + 1) * AST + lrow] = qv.y * 0.125f;
        As[(lcg + 2) * AST + lrow] = qv.z * 0.125f;
        As[(lcg + 3) * AST + lrow] = qv.w * 0.125f;
        __syncthreads();
#pragma unroll
        for (int ss = 0; ss < 16; ss++) {
            ulonglong2 a0 = *(const ulonglong2*)&As[ss * AST + tr * 8];
            ulonglong2 a1 = *(const ulonglong2*)&As[ss * AST + tr * 8 + 4];
            float4 b0 = *(const float4*)&Bs[ss * BST + tc * 4];
            float4 b1 = *(const float4*)&Bs[ss * BST + 128 + tc * 4];
            unsigned long long bs[8] = {splat2(b0.x), splat2(b0.y), splat2(b0.z), splat2(b0.w),
                                        splat2(b1.x), splat2(b1.y), splat2(b1.z), splat2(b1.w)};
#pragma unroll
            for (int j = 0; j < 8; j++) {
                fma2(acc[0][j], a0.x, bs[j]);
                fma2(acc[1][j], a0.y, bs[j]);
                fma2(acc[2][j], a1.x, bs[j]);
                fma2(acc[3][j], a1.y, bs[j]);
            }
        }
        __syncthreads();
    }

    float sc[8][8];
#pragma unroll
    for (int p = 0; p < 4; p++)
#pragma unroll
        for (int j = 0; j < 8; j++) {
            float2 u = unpk(acc[p][j]);
            sc[2 * p + 0][j] = u.x;
            sc[2 * p + 1][j] = u.y;
        }
    const float* sbrow = g_sb + ((size_t)((b * NH + h) * NM) + m0 + tr * 8) * NK;
#pragma unroll
    for (int r = 0; r < 8; r++) {
#pragma unroll
        for (int j = 0; j < 8; j++) {
            int col = (j < 4) ? (tc * 4 + j) : (128 + tc * 4 + (j - 4));
            sc[r][j] += sbrow[(size_t)r * NK + col];
        }
    }
#pragma unroll
    for (int r = 0; r < 8; r++) {
        float mx = sc[r][0];
#pragma unroll
        for (int j = 1; j < 8; j++) mx = fmaxf(mx, sc[r][j]);
#pragma unroll
        for (int off = 16; off > 0; off >>= 1)
            mx = fmaxf(mx, __shfl_xor_sync(0xffffffffu, mx, off));
        float sum = 0.f;
#pragma unroll
        for (int j = 0; j < 8; j++) { sc[r][j] = __expf(sc[r][j] - mx); sum += sc[r][j]; }
#pragma unroll
        for (int off = 16; off > 0; off >>= 1)
            sum += __shfl_xor_sync(0xffffffffu, sum, off);
        float inv = 1.f / sum;
#pragma unroll
        for (int j = 0; j < 8; j++) sc[r][j] *= inv;
    }

    float* attn = sm;               // [64][ATST] overlays As/Bs
    float* Vs = sm + 64 * ATST;     // [16][AST]
#pragma unroll
    for (int r = 0; r < 8; r++) {
#pragma unroll
        for (int j = 0; j < 8; j++) {
            int col = (j < 4) ? (tc * 4 + j) : (128 + tc * 4 + (j - 4));
            attn[(tr * 8 + r) * ATST + col] = sc[r][j];
        }
    }

    const int r2 = tid >> 4, c2 = tid & 15;
    const float* vp = g_vp + (size_t)b * NK * ND + h * NDH;
    float o[4][4];
#pragma unroll
    for (int i = 0; i < 4; i++)
#pragma unroll
        for (int j = 0; j < 4; j++) o[i][j] = 0.f;

    for (int k0 = 0; k0 < NK; k0 += 16) {
        __syncthreads();
        *(float4*)&Vs[(tid >> 4) * AST + ((tid & 15) << 2)] =
            *(const float4*)(vp + (size_t)(k0 + (tid >> 4)) * ND + ((tid & 15) << 2));
        __syncthreads();
#pragma unroll
        for (int j = 0; j < 16; j++) {
            float4 bb = *(const float4*)&Vs[j * AST + c2 * 4];
            float a0 = attn[(r2 * 4 + 0) * ATST + k0 + j];
            float a1 = attn[(r2 * 4 + 1) * ATST + k0 + j];
            float a2 = attn[(r2 * 4 + 2) * ATST + k0 + j];
            float a3 = attn[(r2 * 4 + 3) * ATST + k0 + j];
            o[0][0] += a0 * bb.x; o[0][1] += a0 * bb.y; o[0][2] += a0 * bb.z; o[0][3] += a0 * bb.w;
            o[1][0] += a1 * bb.x; o[1][1] += a1 * bb.y; o[1][2] += a1 * bb.z; o[1][3] += a1 * bb.w;
            o[2][0] += a2 * bb.x; o[2][1] += a2 * bb.y; o[2][2] += a2 * bb.z; o[2][3] += a2 * bb.w;
            o[3][0] += a3 * bb.x; o[3][1] += a3 * bb.y; o[3][2] += a3 * bb.z; o[3][3] += a3 * bb.w;
        }
    }

    float* op = g_o + ((size_t)b * NM + m0) * ND + h * NDH;
#pragma unroll
    for (int i = 0; i < 4; i++) {
        float4 st = make_float4(o[i][0], o[i][1], o[i][2], o[i][3]);
        *(float4*)(op + (size_t)(r2 * 4 + i) * ND + c2 * 4) = st;
    }
}

// ---------------------------------------------------------------------------
extern "C" void kernel_launch(void* const* d_in, const int* in_sizes, int n_in,
                              void* d_out, int out_size)
{
    (void)out_size;
    const float* zp = nullptr;
    const float* geom = nullptr;
    const float* cont = nullptr;
    const float* W[4] = {nullptr, nullptr, nullptr, nullptr};
    const float* bias[4] = {nullptr, nullptr, nullptr, nullptr};
    const float* E[2] = {nullptr, nullptr};
    int wi = 0, bi = 0, ei = 0;
    for (int i = 0; i < n_in; i++) {
        long sz = (long)in_sizes[i];
        if (sz == (long)NB * NM * ND) {
            if (!zp) zp = (const float*)d_in[i];
        } else if (sz == (long)NB * NH * NM * NS) {
            if (!geom) geom = (const float*)d_in[i];
            else if (!cont) cont = (const float*)d_in[i];
        } else if (sz == (long)ND * ND) {
            if (wi < 4) W[wi++] = (const float*)d_in[i];
        } else if (sz == (long)ND) {
            if (bi < 4) bias[bi++] = (const float*)d_in[i];
        } else if (sz == (long)NK * NS) {
            if (ei < 2) E[ei++] = (const float*)d_in[i];
        }
    }
    float* out = (float*)d_out;

    float* sbp;
    cudaGetSymbolAddress((void**)&sbp, g_sb);

    cudaFuncSetAttribute(k_bias256, cudaFuncAttributeMaxDynamicSharedMemorySize, SMP2);
    cudaFuncSetAttribute(k_qkv16, cudaFuncAttributeMaxDynamicSharedMemorySize, SM16);
    cudaFuncSetAttribute(k_proj16s, cudaFuncAttributeMaxDynamicSharedMemorySize, SM16);
    cudaFuncSetAttribute(k_out16, cudaFuncAttributeMaxDynamicSharedMemorySize, SM16);
    cudaFuncSetAttribute(attn2, cudaFuncAttributeMaxDynamicSharedMemorySize,
                         SMF_FLOATS * (int)sizeof(float));

    dim3 thr(256);
    // Ek -> fp16 table
    k_cvt<<<NK * NS / 2 / 256, thr>>>(E[0]);
    // bias scores: (geom+cont)[65536,2048] @ Ek^T -> g_sb (512-thread CTAs)
    k_bias256<<<dim3(NB * NH * NM / BM), dim3(512), SMP2>>>(geom, cont, sbp);
    // q/k/v projections; k,v written transposed for the proj NT GEMMs
    k_qkv16<<<dim3(NB * NM / BM, ND / BN, 3), thr, SM16>>>(zp, W[0], W[1], W[2],
                                                            bias[0], bias[1], bias[2]);
    // Linformer projections (split-K x4) + reduce
    k_proj16s<<<dim3(NK / BM, ND / BN, 16), thr, SM16>>>(E[0], E[1]);
    k_projred<<<4 * NK * ND / 256, thr>>>();
    // fused attention
    attn2<<<dim3(NM / 64, NH, NB), thr, SMF_FLOATS * sizeof(float)>>>();
    // output projection
    k_out16<<<dim3(NB * NM / BM, ND / BN), thr, SM16>>>(W[3], bias[3], out);
}

// round 13
// speedup vs baseline: 1.3473x; 1.3473x over previous
#include <cuda_runtime.h>

#define NB 2
#define NH 16
#define NM 2048
#define ND 1024
#define NDH 64
#define NS 2048
#define NK 256

// Scratch (device globals; no allocations allowed)
__device__ float g_q[NB * NM * ND];
__device__ float g_kt[NB * ND * NM];               // k transposed [b][d][m]
__device__ float g_vt[NB * ND * NM];               // v transposed [b][d][m]
__device__ float g_o[NB * NM * ND];
__device__ float g_kp[NB * NK * ND];               // k proj [b][k][d]
__device__ float g_vp[NB * NK * ND];               // v proj [b][k][d]
__device__ float g_sb[NB * NH * NM * NK];          // bias scores [B,H,M,K]
__device__ float g_pp[16 * NK * ND];               // proj split-K partials
__device__ __align__(16) unsigned short g_ek16[NK * NS];   // Ek as fp16

// ---------------- packed f32x2 helpers (attn2) ----------------
static __device__ __forceinline__ unsigned long long splat2(float x) {
    unsigned long long r;
    asm("mov.b64 %0, {%1, %1};" : "=l"(r) : "f"(x));
    return r;
}
static __device__ __forceinline__ void fma2(unsigned long long &c,
                                            unsigned long long a,
                                            unsigned long long b) {
    asm("fma.rn.f32x2 %0, %1, %2, %0;" : "+l"(c) : "l"(a), "l"(b));
}
static __device__ __forceinline__ float2 unpk(unsigned long long v) {
    float2 f;
    asm("mov.b64 {%0, %1}, %2;" : "=f"(f.x), "=f"(f.y) : "l"(v));
    return f;
}

// ---------------- fp16 mma helpers ----------------
static __device__ __forceinline__ unsigned s2u(const void* p) {
    unsigned a;
    asm("{ .reg .u64 t; cvta.to.shared.u64 t, %1; cvt.u32.u64 %0, t; }" : "=r"(a) : "l"(p));
    return a;
}
static __device__ __forceinline__ unsigned pack2(float lo, float hi) {
    unsigned r;
    asm("cvt.rn.f16x2.f32 %0, %1, %2;" : "=r"(r) : "f"(hi), "f"(lo));
    return r;
}
static __device__ __forceinline__ void ldm4(unsigned* r, unsigned a) {
    asm volatile("ldmatrix.sync.aligned.m8n8.x4.shared.b16 {%0,%1,%2,%3}, [%4];"
                 : "=r"(r[0]), "=r"(r[1]), "=r"(r[2]), "=r"(r[3]) : "r"(a));
}
static __device__ __forceinline__ void mma16(float* c, const unsigned* a,
                                             unsigned b0, unsigned b1) {
    asm volatile(
        "mma.sync.aligned.m16n8k16.row.col.f32.f16.f16.f32 "
        "{%0,%1,%2,%3}, {%4,%5,%6,%7}, {%8,%9}, {%0,%1,%2,%3};"
        : "+f"(c[0]), "+f"(c[1]), "+f"(c[2]), "+f"(c[3])
        : "r"(a[0]), "r"(a[1]), "r"(a[2]), "r"(a[3]), "r"(b0), "r"(b1));
}
static __device__ __forceinline__ void cpa16(unsigned dst, const void* src) {
    asm volatile("cp.async.cg.shared.global [%0], [%1], 16;" :: "r"(dst), "l"(src) : "memory");
}

#define BM 128
#define BN 128
#define BK 64
#define BKH 72                         // padded half stride
#define TILEH (128 * BKH)              // 9216 halves per tile
#define SM16 (4 * TILEH * 2)           // 73728 bytes

// ---------------------------------------------------------------------------
// tc16_body: C tile [128x128] = A @ B^T (+bias) via fp16 m16n8k16, fp32 accum.
// KdS = row stride of A and B; Kd = K-length to accumulate (Kd <= KdS slice).
// If Ct != nullptr: write transposed Ct[(n0+c)*CtStride + m_local].
// ---------------------------------------------------------------------------
static __device__ __forceinline__ void tc16_body(
    const float* __restrict__ A, const float* __restrict__ Bm,
    const float* __restrict__ bias, float* __restrict__ C, int Nld,
    int Kd, int KdS, int bx, int by, float* __restrict__ Ct, int CtStride)
{
    extern __shared__ unsigned short smh[];
    const unsigned sbase = s2u(smh);
    const int tid = threadIdx.x, lane = tid & 31, wid = tid >> 5;
    const size_t m0 = (size_t)bx * BM;
    const int n0 = by * BN;

    const int ldr = tid >> 3, ldc = (tid & 7) * 8;
    const float* Ag = A + (m0 + ldr) * (size_t)KdS + ldc;
    const float* Bg = Bm + (size_t)(n0 + ldr) * KdS + ldc;
    const unsigned sOff = (unsigned)(ldr * BKH + ldc) * 2;

    auto ld = [&](int k0, int buf) {
        unsigned ab = sbase + (unsigned)(buf * 2 * TILEH) * 2 + sOff;
        unsigned bb = ab + (unsigned)TILEH * 2;
#pragma unroll
        for (int j = 0; j < 4; j++) {
            const size_t ro = (size_t)(j * 32) * KdS;
            const unsigned so = (unsigned)(j * 32 * BKH) * 2;
#pragma unroll
            for (int h = 0; h < 2; h++) {
                float4 v = *(const float4*)(Ag + ro + k0 + h * 4);
                unsigned u0 = pack2(v.x, v.y), u1 = pack2(v.z, v.w);
                asm volatile("st.shared.v2.b32 [%0], {%1,%2};"
                             :: "r"(ab + so + h * 8), "r"(u0), "r"(u1) : "memory");
                float4 t = *(const float4*)(Bg + ro + k0 + h * 4);
                unsigned w0 = pack2(t.x, t.y), w1 = pack2(t.z, t.w);
                asm volatile("st.shared.v2.b32 [%0], {%1,%2};"
                             :: "r"(bb + so + h * 8), "r"(w0), "r"(w1) : "memory");
            }
        }
    };

    const int wm = (wid >> 2) * 64, wn = (wid & 3) * 32;
    const int gr = lane >> 2, gc = lane & 3;
    const unsigned frow = (unsigned)(lane & 15), fcol = (unsigned)((lane >> 4) * 8);

    float acc[4][4][4];
#pragma unroll
    for (int mt = 0; mt < 4; mt++)
#pragma unroll
        for (int nt = 0; nt < 4; nt++)
#pragma unroll
            for (int e = 0; e < 4; e++) acc[mt][nt][e] = 0.f;

    ld(0, 0);
    __syncthreads();

    const int nk = Kd / BK;
    for (int i = 0; i < nk; i++) {
        if (i + 1 < nk) ld((i + 1) * BK, (i + 1) & 1);
        const unsigned tb = sbase + (unsigned)((i & 1) * 2 * TILEH) * 2;
#pragma unroll
        for (int k16 = 0; k16 < BK; k16 += 16) {
            unsigned af[4][4], bf[4][2];
#pragma unroll
            for (int mt = 0; mt < 4; mt++) {
                unsigned a = tb + ((unsigned)(wm + mt * 16 + frow) * BKH + k16 + fcol) * 2;
                ldm4(af[mt], a);
            }
#pragma unroll
            for (int np = 0; np < 2; np++) {
                unsigned a = tb + (unsigned)TILEH * 2 +
                             ((unsigned)(wn + np * 16 + frow) * BKH + k16 + fcol) * 2;
                unsigned r[4];
                ldm4(r, a);
                bf[2 * np + 0][0] = r[0]; bf[2 * np + 1][0] = r[1];
                bf[2 * np + 0][1] = r[2]; bf[2 * np + 1][1] = r[3];
            }
#pragma unroll
            for (int mt = 0; mt < 4; mt++)
#pragma unroll
                for (int nt = 0; nt < 4; nt++)
                    mma16(acc[mt][nt], af[mt], bf[nt][0], bf[nt][1]);
        }
        __syncthreads();
    }

    if (!Ct) {
#pragma unroll
        for (int mt = 0; mt < 4; mt++) {
            const size_t r = m0 + wm + mt * 16 + gr;
            float* cp0 = C + r * (size_t)Nld;
            float* cp1 = C + (r + 8) * (size_t)Nld;
#pragma unroll
            for (int nt = 0; nt < 4; nt++) {
                const int c = n0 + wn + nt * 8 + 2 * gc;
                float b0 = bias ? bias[c] : 0.f;
                float b1 = bias ? bias[c + 1] : 0.f;
                *(float2*)(cp0 + c) = make_float2(acc[mt][nt][0] + b0, acc[mt][nt][1] + b1);
                *(float2*)(cp1 + c) = make_float2(acc[mt][nt][2] + b0, acc[mt][nt][3] + b1);
            }
        }
    } else {
        float* st32 = (float*)smh;   // [128][132]
        __syncthreads();
#pragma unroll
        for (int mt = 0; mt < 4; mt++) {
            const int r0 = wm + mt * 16 + gr;
#pragma unroll
            for (int nt = 0; nt < 4; nt++) {
                const int c = wn + nt * 8 + 2 * gc;
                float b0 = bias ? bias[n0 + c] : 0.f;
                float b1 = bias ? bias[n0 + c + 1] : 0.f;
                st32[r0 * 132 + c] = acc[mt][nt][0] + b0;
                st32[r0 * 132 + c + 1] = acc[mt][nt][1] + b1;
                st32[(r0 + 8) * 132 + c] = acc[mt][nt][2] + b0;
                st32[(r0 + 8) * 132 + c + 1] = acc[mt][nt][3] + b1;
            }
        }
        __syncthreads();
#pragma unroll
        for (int i = 0; i < 16; i++) {
            const int c = wid * 16 + i;
            float4 o;
            o.x = st32[(lane * 4 + 0) * 132 + c];
            o.y = st32[(lane * 4 + 1) * 132 + c];
            o.z = st32[(lane * 4 + 2) * 132 + c];
            o.w = st32[(lane * 4 + 3) * 132 + c];
            *(float4*)(Ct + (size_t)(n0 + c) * CtStride + lane * 4) = o;
        }
        __syncthreads();
    }
}

__global__ __launch_bounds__(256) void k_qkv16(const float* __restrict__ z,
                                               const float* __restrict__ W0,
                                               const float* __restrict__ W1,
                                               const float* __restrict__ W2,
                                               const float* __restrict__ b0,
                                               const float* __restrict__ b1,
                                               const float* __restrict__ b2)
{
    const int zz = blockIdx.z;
    const float* W = (zz == 0) ? W0 : (zz == 1) ? W1 : W2;
    const float* bb = (zz == 0) ? b0 : (zz == 1) ? b1 : b2;
    if (zz == 0) {
        tc16_body(z, W, bb, g_q, ND, ND, ND, blockIdx.x, blockIdx.y, nullptr, 0);
    } else {
        const int b = blockIdx.x >> 4;
        const int mloc = (blockIdx.x & 15) * BM;
        float* base = ((zz == 1) ? g_kt : g_vt) + (size_t)b * ND * NM + mloc;
        tc16_body(z, W, bb, nullptr, 0, ND, ND, blockIdx.x, blockIdx.y, base, NM);
    }
}

// proj split-K x4: z = gemm*4 + split; gemm 0,1 = Ek@kt[b]^T, 2,3 = Ev@vt[b]^T
__global__ __launch_bounds__(256) void k_proj16s(const float* __restrict__ Ek,
                                                 const float* __restrict__ Ev)
{
    const int bz = blockIdx.z;
    const int zz = bz >> 2, sp = bz & 3;
    const int koff = sp * 512;
    const float* A = ((zz < 2) ? Ek : Ev) + koff;
    const float* Bm = (((zz < 2) ? g_kt : g_vt) + (size_t)(zz & 1) * ND * NM) + koff;
    float* C = g_pp + (size_t)bz * (NK * ND);
    tc16_body(A, Bm, nullptr, C, ND, 512, NM, blockIdx.x, blockIdx.y, nullptr, 0);
}

__global__ __launch_bounds__(256) void k_projred()
{
    const size_t i = (size_t)blockIdx.x * 256 + threadIdx.x;   // over 4*NK*ND
    const int zz = (int)(i / (NK * ND));
    const size_t r = i - (size_t)zz * (NK * ND);
    const size_t base = (size_t)(zz * 4) * (NK * ND) + r;
    float s = g_pp[base] + g_pp[base + (size_t)NK * ND] +
              g_pp[base + 2 * (size_t)NK * ND] + g_pp[base + 3 * (size_t)NK * ND];
    float* dst = (zz < 2) ? g_kp : g_vp;
    dst[(size_t)(zz & 1) * NK * ND + r] = s;
}

__global__ __launch_bounds__(256) void k_out16(const float* __restrict__ Wo,
                                               const float* __restrict__ bo,
                                               float* __restrict__ out)
{
    tc16_body(g_o, Wo, bo, out, ND, ND, ND, blockIdx.x, blockIdx.y, nullptr, 0);
}

// ---------------------------------------------------------------------------
// k_cvt: Ek fp32 -> fp16 table (once)
// ---------------------------------------------------------------------------
__global__ __launch_bounds__(256) void k_cvt(const float* __restrict__ Ek)
{
    const int i = blockIdx.x * 256 + threadIdx.x;   // over NK*NS/2
    float2 v = *(const float2*)(Ek + 2 * (size_t)i);
    *(unsigned*)(g_ek16 + 2 * (size_t)i) = pack2(v.x, v.y);
}

// ---------------------------------------------------------------------------
// k_bias256 (R11 v2, 256 threads): 128x256 tile, BK=32, software-pipelined.
//   B (Ek16) via cp.async; A (geom+cont) LDG-staged in registers across the
//   MMA section. Warp tile 64x64 (acc[4][8][4]).
// ---------------------------------------------------------------------------
#define BK2 32
#define BKH2 40                        // padded half stride (80 B)
#define A2T (128 * BKH2)               // 5120 halves per A buffer
#define B2T (256 * BKH2)               // 10240 halves per B buffer
#define SMP2 ((2 * A2T + 2 * B2T) * 2) // 61440 bytes

__global__ __launch_bounds__(256) void k_bias256(const float* __restrict__ geom,
                                                 const float* __restrict__ cont,
                                                 float* __restrict__ sb)
{
    extern __shared__ unsigned short smh[];
    const unsigned sbase = s2u(smh);
    const unsigned bbase = sbase + (unsigned)(2 * A2T) * 2;
    const int tid = threadIdx.x, lane = tid & 31, wid = tid >> 5;
    const size_t m0 = (size_t)blockIdx.x * BM;      // row in flattened [B*H*M]

    // A loader: row = tid>>1, col half = (tid&1)*16
    const int ar = tid >> 1, ac = (tid & 1) * 16;
    const float* Ag = geom + (m0 + ar) * (size_t)NS + ac;
    const float* Cg = cont + (m0 + ar) * (size_t)NS + ac;
    const unsigned aoff = (unsigned)(ar * BKH2 + ac) * 2;
    // B loader: row = tid, 4 x 16B cp.async
    const unsigned short* Bg = g_ek16 + (size_t)tid * NS;
    const unsigned boff = (unsigned)(tid * BKH2) * 2;

    float4 sg[4], sc[4];   // A staging (32 regs)

    auto ldgA = [&](int k0) {
#pragma unroll
        for (int j = 0; j < 4; j++) sg[j] = *(const float4*)(Ag + k0 + j * 4);
#pragma unroll
        for (int j = 0; j < 4; j++) sc[j] = *(const float4*)(Cg + k0 + j * 4);
    };
    auto stsA = [&](int buf) {
        unsigned ab = sbase + (unsigned)(buf * A2T) * 2 + aoff;
#pragma unroll
        for (int j = 0; j < 2; j++) {
            unsigned p0 = pack2(sg[2 * j].x + sc[2 * j].x, sg[2 * j].y + sc[2 * j].y);
            unsigned p1 = pack2(sg[2 * j].z + sc[2 * j].z, sg[2 * j].w + sc[2 * j].w);
            unsigned p2 = pack2(sg[2 * j + 1].x + sc[2 * j + 1].x, sg[2 * j + 1].y + sc[2 * j + 1].y);
            unsigned p3 = pack2(sg[2 * j + 1].z + sc[2 * j + 1].z, sg[2 * j + 1].w + sc[2 * j + 1].w);
            asm volatile("st.shared.v4.b32 [%0], {%1,%2,%3,%4};"
                         :: "r"(ab + j * 16), "r"(p0), "r"(p1), "r"(p2), "r"(p3) : "memory");
        }
    };
    auto cpB = [&](int k0, int buf) {
        unsigned bb = bbase + (unsigned)(buf * B2T) * 2 + boff;
#pragma unroll
        for (int j = 0; j < 4; j++)
            cpa16(bb + j * 16, Bg + k0 + j * 8);
    };

    const int wm = (wid >> 2) * 64, wn = (wid & 3) * 64;
    const int gr = lane >> 2, gc = lane & 3;
    const unsigned frow = (unsigned)(lane & 15), fcol = (unsigned)((lane >> 4) * 8);

    float acc[4][8][4];
#pragma unroll
    for (int mt = 0; mt < 4; mt++)
#pragma unroll
        for (int nt = 0; nt < 8; nt++)
#pragma unroll
            for (int e = 0; e < 4; e++) acc[mt][nt][e] = 0.f;

    // prologue
    cpB(0, 0);
    asm volatile("cp.async.commit_group;" ::: "memory");
    ldgA(0);
    stsA(0);
    asm volatile("cp.async.wait_group 0;" ::: "memory");
    __syncthreads();

    const int nk = NS / BK2;   // 64
    for (int i = 0; i < nk; i++) {
        if (i + 1 < nk) {
            ldgA((i + 1) * BK2);                       // LDGs in flight over MMA
            cpB((i + 1) * BK2, (i + 1) & 1);
            asm volatile("cp.async.commit_group;" ::: "memory");
        }
        const unsigned ta = sbase + (unsigned)((i & 1) * A2T) * 2;
        const unsigned tb = bbase + (unsigned)((i & 1) * B2T) * 2;
#pragma unroll
        for (int k16 = 0; k16 < BK2; k16 += 16) {
            unsigned af[4][4], bf[8][2];
#pragma unroll
            for (int mt = 0; mt < 4; mt++) {
                unsigned a = ta + ((unsigned)(wm + mt * 16 + frow) * BKH2 + k16 + fcol) * 2;
                ldm4(af[mt], a);
            }
#pragma unroll
            for (int np = 0; np < 4; np++) {
                unsigned a = tb + ((unsigned)(wn + np * 16 + frow) * BKH2 + k16 + fcol) * 2;
                unsigned r[4];
                ldm4(r, a);
                bf[2 * np + 0][0] = r[0]; bf[2 * np + 1][0] = r[1];
                bf[2 * np + 0][1] = r[2]; bf[2 * np + 1][1] = r[3];
            }
#pragma unroll
            for (int mt = 0; mt < 4; mt++)
#pragma unroll
                for (int nt = 0; nt < 8; nt++)
                    mma16(acc[mt][nt], af[mt], bf[nt][0], bf[nt][1]);
        }
        if (i + 1 < nk) {
            stsA((i + 1) & 1);                         // consume staged LDGs
            asm volatile("cp.async.wait_group 0;" ::: "memory");
        }
        __syncthreads();
    }

#pragma unroll
    for (int mt = 0; mt < 4; mt++) {
        const size_t r = m0 + wm + mt * 16 + gr;
        float* cp0 = sb + r * (size_t)NK;
        float* cp1 = sb + (r + 8) * (size_t)NK;
#pragma unroll
        for (int nt = 0; nt < 8; nt++) {
            const int c = wn + nt * 8 + 2 * gc;
            *(float2*)(cp0 + c) = make_float2(acc[mt][nt][0], acc[mt][nt][1]);
            *(float2*)(cp1 + c) = make_float2(acc[mt][nt][2], acc[mt][nt][3]);
        }
    }
}

// ---------------------------------------------------------------------------
// Fused attention per (b, h, 64-row m tile)  (R7 version):
//   scores[64,256] = g_sb + (q/8)[64,64] @ kproj^T ; softmax; attn @ vproj
// ---------------------------------------------------------------------------
#define AST 72
#define BST 264
#define ATST 264
#define SMF_FLOATS (64 * ATST + 16 * AST)   // 18048 floats = 72192 B

__global__ __launch_bounds__(256) void attn2()
{
    extern __shared__ float sm[];
    float* As = sm;                 // [16][AST]
    float* Bs = sm + 16 * AST;      // [16][BST]
    const int m0 = blockIdx.x * 64;
    const int h = blockIdx.y, b = blockIdx.z;
    const int tid = threadIdx.x;
    const int tr = tid >> 5, tc = tid & 31;
    const int lrow = tid >> 2, lcg = (tid & 3) << 2;

    unsigned long long acc[4][8];
#pragma unroll
    for (int p = 0; p < 4; p++)
#pragma unroll
        for (int j = 0; j < 8; j++) acc[p][j] = 0ull;

    const float* qp = g_q + ((size_t)b * NM + m0) * ND + h * NDH;
    const float* kp = g_kp + ((size_t)b * NK + tid) * ND + h * NDH;
    for (int d0 = 0; d0 < NDH; d0 += 16) {
        const float* ep = kp + d0;
        float4 e0 = *(const float4*)(ep + 0);
        float4 e1 = *(const float4*)(ep + 4);
        float4 e2 = *(const float4*)(ep + 8);
        float4 e3 = *(const float4*)(ep + 12);
        Bs[0 * BST + tid] = e0.x;  Bs[1 * BST + tid] = e0.y;
        Bs[2 * BST + tid] = e0.z;  Bs[3 * BST + tid] = e0.w;
        Bs[4 * BST + tid] = e1.x;  Bs[5 * BST + tid] = e1.y;
        Bs[6 * BST + tid] = e1.z;  Bs[7 * BST + tid] = e1.w;
        Bs[8 * BST + tid] = e2.x;  Bs[9 * BST + tid] = e2.y;
        Bs[10 * BST + tid] = e2.z; Bs[11 * BST + tid] = e2.w;
        Bs[12 * BST + tid] = e3.x; Bs[13 * BST + tid] = e3.y;
        Bs[14 * BST + tid] = e3.z; Bs[15 * BST + tid] = e3.w;

        float4 qv = *(const float4*)(qp + (size_t)lrow * ND + d0 + lcg);
        As[(lcg + 0) * AST + lrow] = qv.x * 0.125f;
        As[(lcg + 1) * AST + lrow] = qv.y * 0.125f;
        As[(lcg + 2) * AST + lrow] = qv.z * 0.125f;
        As[(lcg + 3) * AST + lrow] = qv.w * 0.125f;
        __syncthreads();
#pragma unroll
        for (int ss = 0; ss < 16; ss++) {
            ulonglong2 a0 = *(const ulonglong2*)&As[ss * AST + tr * 8];
            ulonglong2 a1 = *(const ulonglong2*)&As[ss * AST + tr * 8 + 4];
            float4 b0 = *(const float4*)&Bs[ss * BST + tc * 4];
            float4 b1 = *(const float4*)&Bs[ss * BST + 128 + tc * 4];
            unsigned long long bs[8] = {splat2(b0.x), splat2(b0.y), splat2(b0.z), splat2(b0.w),
                                        splat2(b1.x), splat2(b1.y), splat2(b1.z), splat2(b1.w)};
#pragma unroll
            for (int j = 0; j < 8; j++) {
                fma2(acc[0][j], a0.x, bs[j]);
                fma2(acc[1][j], a0.y, bs[j]);
                fma2(acc[2][j], a1.x, bs[j]);
                fma2(acc[3][j], a1.y, bs[j]);
            }
        }
        __syncthreads();
    }

    float sc[8][8];
#pragma unroll
    for (int p = 0; p < 4; p++)
#pragma unroll
        for (int j = 0; j < 8; j++) {
            float2 u = unpk(acc[p][j]);
            sc[2 * p + 0][j] = u.x;
            sc[2 * p + 1][j] = u.y;
        }
    const float* sbrow = g_sb + ((size_t)((b * NH + h) * NM) + m0 + tr * 8) * NK;
#pragma unroll
    for (int r = 0; r < 8; r++) {
#pragma unroll
        for (int j = 0; j < 8; j++) {
            int col = (j < 4) ? (tc * 4 + j) : (128 + tc * 4 + (j - 4));
            sc[r][j] += sbrow[(size_t)r * NK + col];
        }
    }
#pragma unroll
    for (int r = 0; r < 8; r++) {
        float mx = sc[r][0];
#pragma unroll
        for (int j = 1; j < 8; j++) mx = fmaxf(mx, sc[r][j]);
#pragma unroll
        for (int off = 16; off > 0; off >>= 1)
            mx = fmaxf(mx, __shfl_xor_sync(0xffffffffu, mx, off));
        float sum = 0.f;
#pragma unroll
        for (int j = 0; j < 8; j++) { sc[r][j] = __expf(sc[r][j] - mx); sum += sc[r][j]; }
#pragma unroll
        for (int off = 16; off > 0; off >>= 1)
            sum += __shfl_xor_sync(0xffffffffu, sum, off);
        float inv = 1.f / sum;
#pragma unroll
        for (int j = 0; j < 8; j++) sc[r][j] *= inv;
    }

    float* attn = sm;               // [64][ATST] overlays As/Bs
    float* Vs = sm + 64 * ATST;     // [16][AST]
#pragma unroll
    for (int r = 0; r < 8; r++) {
#pragma unroll
        for (int j = 0; j < 8; j++) {
            int col = (j < 4) ? (tc * 4 + j) : (128 + tc * 4 + (j - 4));
            attn[(tr * 8 + r) * ATST + col] = sc[r][j];
        }
    }

    const int r2 = tid >> 4, c2 = tid & 15;
    const float* vp = g_vp + (size_t)b * NK * ND + h * NDH;
    float o[4][4];
#pragma unroll
    for (int i = 0; i < 4; i++)
#pragma unroll
        for (int j = 0; j < 4; j++) o[i][j] = 0.f;

    for (int k0 = 0; k0 < NK; k0 += 16) {
        __syncthreads();
        *(float4*)&Vs[(tid >> 4) * AST + ((tid & 15) << 2)] =
            *(const float4*)(vp + (size_t)(k0 + (tid >> 4)) * ND + ((tid & 15) << 2));
        __syncthreads();
#pragma unroll
        for (int j = 0; j < 16; j++) {
            float4 bb = *(const float4*)&Vs[j * AST + c2 * 4];
            float a0 = attn[(r2 * 4 + 0) * ATST + k0 + j];
            float a1 = attn[(r2 * 4 + 1) * ATST + k0 + j];
            float a2 = attn[(r2 * 4 + 2) * ATST + k0 + j];
            float a3 = attn[(r2 * 4 + 3) * ATST + k0 + j];
            o[0][0] += a0 * bb.x; o[0][1] += a0 * bb.y; o[0][2] += a0 * bb.z; o[0][3] += a0 * bb.w;
            o[1][0] += a1 * bb.x; o[1][1] += a1 * bb.y; o[1][2] += a1 * bb.z; o[1][3] += a1 * bb.w;
            o[2][0] += a2 * bb.x; o[2][1] += a2 * bb.y; o[2][2] += a2 * bb.z; o[2][3] += a2 * bb.w;
            o[3][0] += a3 * bb.x; o[3][1] += a3 * bb.y; o[3][2] += a3 * bb.z; o[3][3] += a3 * bb.w;
        }
    }

    float* op = g_o + ((size_t)b * NM + m0) * ND + h * NDH;
#pragma unroll
    for (int i = 0; i < 4; i++) {
        float4 st = make_float4(o[i][0], o[i][1], o[i][2], o[i][3]);
        *(float4*)(op + (size_t)(r2 * 4 + i) * ND + c2 * 4) = st;
    }
}

// ---------------------------------------------------------------------------
extern "C" void kernel_launch(void* const* d_in, const int* in_sizes, int n_in,
                              void* d_out, int out_size)
{
    (void)out_size;
    const float* zp = nullptr;
    const float* geom = nullptr;
    const float* cont = nullptr;
    const float* W[4] = {nullptr, nullptr, nullptr, nullptr};
    const float* bias[4] = {nullptr, nullptr, nullptr, nullptr};
    const float* E[2] = {nullptr, nullptr};
    int wi = 0, bi = 0, ei = 0;
    for (int i = 0; i < n_in; i++) {
        long sz = (long)in_sizes[i];
        if (sz == (long)NB * NM * ND) {
            if (!zp) zp = (const float*)d_in[i];
        } else if (sz == (long)NB * NH * NM * NS) {
            if (!geom) geom = (const float*)d_in[i];
            else if (!cont) cont = (const float*)d_in[i];
        } else if (sz == (long)ND * ND) {
            if (wi < 4) W[wi++] = (const float*)d_in[i];
        } else if (sz == (long)ND) {
            if (bi < 4) bias[bi++] = (const float*)d_in[i];
        } else if (sz == (long)NK * NS) {
            if (ei < 2) E[ei++] = (const float*)d_in[i];
        }
    }
    float* out = (float*)d_out;

    float* sbp;
    cudaGetSymbolAddress((void**)&sbp, g_sb);

    cudaFuncSetAttribute(k_bias256, cudaFuncAttributeMaxDynamicSharedMemorySize, SMP2);
    cudaFuncSetAttribute(k_qkv16, cudaFuncAttributeMaxDynamicSharedMemorySize, SM16);
    cudaFuncSetAttribute(k_proj16s, cudaFuncAttributeMaxDynamicSharedMemorySize, SM16);
    cudaFuncSetAttribute(k_out16, cudaFuncAttributeMaxDynamicSharedMemorySize, SM16);
    cudaFuncSetAttribute(attn2, cudaFuncAttributeMaxDynamicSharedMemorySize,
                         SMF_FLOATS * (int)sizeof(float));

    dim3 thr(256);
    // Ek -> fp16 table
    k_cvt<<<NK * NS / 2 / 256, thr>>>(E[0]);
    // bias scores: (geom+cont)[65536,2048] @ Ek^T -> g_sb
    k_bias256<<<dim3(NB * NH * NM / BM), thr, SMP2>>>(geom, cont, sbp);
    // q/k/v projections; k,v written transposed for the proj NT GEMMs
    k_qkv16<<<dim3(NB * NM / BM, ND / BN, 3), thr, SM16>>>(zp, W[0], W[1], W[2],
                                                            bias[0], bias[1], bias[2]);
    // Linformer projections (split-K x4) + reduce
    k_proj16s<<<dim3(NK / BM, ND / BN, 16), thr, SM16>>>(E[0], E[1]);
    k_projred<<<4 * NK * ND / 256, thr>>>();
    // fused attention
    attn2<<<dim3(NM / 64, NH, NB), thr, SMF_FLOATS * sizeof(float)>>>();
    // output projection
    k_out16<<<dim3(NB * NM / BM, ND / BN), thr, SM16>>>(W[3], bias[3], out);
}

// round 14
// speedup vs baseline: 1.4598x; 1.0835x over previous
#include <cuda_runtime.h>

#define NB 2
#define NH 16
#define NM 2048
#define ND 1024
#define NDH 64
#define NS 2048
#define NK 256

// Scratch (device globals; no allocations allowed)
__device__ float g_q[NB * NM * ND];
__device__ float g_kt[NB * ND * NM];               // k transposed [b][d][m]
__device__ float g_vt[NB * ND * NM];               // v transposed [b][d][m]
__device__ float g_o[NB * NM * ND];
__device__ float g_kp[NB * NK * ND];               // k proj [b][k][d]
__device__ float g_vpt[NB * ND * NK];              // v proj transposed [b][d][k]
__device__ float g_sb[NB * NH * NM * NK];          // bias scores [B,H,M,K]
__device__ float g_pp[16 * NK * ND];               // proj split-K partials
__device__ __align__(16) unsigned short g_ek16[NK * NS];   // Ek as fp16

// ---------------- fp16 mma helpers ----------------
static __device__ __forceinline__ unsigned s2u(const void* p) {
    unsigned a;
    asm("{ .reg .u64 t; cvta.to.shared.u64 t, %1; cvt.u32.u64 %0, t; }" : "=r"(a) : "l"(p));
    return a;
}
static __device__ __forceinline__ unsigned pack2(float lo, float hi) {
    unsigned r;
    asm("cvt.rn.f16x2.f32 %0, %1, %2;" : "=r"(r) : "f"(hi), "f"(lo));
    return r;
}
static __device__ __forceinline__ void ldm4(unsigned* r, unsigned a) {
    asm volatile("ldmatrix.sync.aligned.m8n8.x4.shared.b16 {%0,%1,%2,%3}, [%4];"
                 : "=r"(r[0]), "=r"(r[1]), "=r"(r[2]), "=r"(r[3]) : "r"(a));
}
static __device__ __forceinline__ void mma16(float* c, const unsigned* a,
                                             unsigned b0, unsigned b1) {
    asm volatile(
        "mma.sync.aligned.m16n8k16.row.col.f32.f16.f16.f32 "
        "{%0,%1,%2,%3}, {%4,%5,%6,%7}, {%8,%9}, {%0,%1,%2,%3};"
        : "+f"(c[0]), "+f"(c[1]), "+f"(c[2]), "+f"(c[3])
        : "r"(a[0]), "r"(a[1]), "r"(a[2]), "r"(a[3]), "r"(b0), "r"(b1));
}
static __device__ __forceinline__ void cpa16(unsigned dst, const void* src) {
    asm volatile("cp.async.cg.shared.global [%0], [%1], 16;" :: "r"(dst), "l"(src) : "memory");
}

#define BM 128
#define BN 128
#define BK 64
#define BKH 72                         // padded half stride
#define TILEH (128 * BKH)              // 9216 halves per tile
#define SM16 (4 * TILEH * 2)           // 73728 bytes

// ---------------------------------------------------------------------------
// tc16_body: C tile [128x128] = A @ B^T (+bias) via fp16 m16n8k16, fp32 accum.
// KdS = row stride of A and B; Kd = K-length to accumulate (Kd <= KdS slice).
// If Ct != nullptr: write transposed Ct[(n0+c)*CtStride + m_local].
// ---------------------------------------------------------------------------
static __device__ __forceinline__ void tc16_body(
    const float* __restrict__ A, const float* __restrict__ Bm,
    const float* __restrict__ bias, float* __restrict__ C, int Nld,
    int Kd, int KdS, int bx, int by, float* __restrict__ Ct, int CtStride)
{
    extern __shared__ unsigned short smh[];
    const unsigned sbase = s2u(smh);
    const int tid = threadIdx.x, lane = tid & 31, wid = tid >> 5;
    const size_t m0 = (size_t)bx * BM;
    const int n0 = by * BN;

    const int ldr = tid >> 3, ldc = (tid & 7) * 8;
    const float* Ag = A + (m0 + ldr) * (size_t)KdS + ldc;
    const float* Bg = Bm + (size_t)(n0 + ldr) * KdS + ldc;
    const unsigned sOff = (unsigned)(ldr * BKH + ldc) * 2;

    auto ld = [&](int k0, int buf) {
        unsigned ab = sbase + (unsigned)(buf * 2 * TILEH) * 2 + sOff;
        unsigned bb = ab + (unsigned)TILEH * 2;
#pragma unroll
        for (int j = 0; j < 4; j++) {
            const size_t ro = (size_t)(j * 32) * KdS;
            const unsigned so = (unsigned)(j * 32 * BKH) * 2;
#pragma unroll
            for (int h = 0; h < 2; h++) {
                float4 v = *(const float4*)(Ag + ro + k0 + h * 4);
                unsigned u0 = pack2(v.x, v.y), u1 = pack2(v.z, v.w);
                asm volatile("st.shared.v2.b32 [%0], {%1,%2};"
                             :: "r"(ab + so + h * 8), "r"(u0), "r"(u1) : "memory");
                float4 t = *(const float4*)(Bg + ro + k0 + h * 4);
                unsigned w0 = pack2(t.x, t.y), w1 = pack2(t.z, t.w);
                asm volatile("st.shared.v2.b32 [%0], {%1,%2};"
                             :: "r"(bb + so + h * 8), "r"(w0), "r"(w1) : "memory");
            }
        }
    };

    const int wm = (wid >> 2) * 64, wn = (wid & 3) * 32;
    const int gr = lane >> 2, gc = lane & 3;
    const unsigned frow = (unsigned)(lane & 15), fcol = (unsigned)((lane >> 4) * 8);

    float acc[4][4][4];
#pragma unroll
    for (int mt = 0; mt < 4; mt++)
#pragma unroll
        for (int nt = 0; nt < 4; nt++)
#pragma unroll
            for (int e = 0; e < 4; e++) acc[mt][nt][e] = 0.f;

    ld(0, 0);
    __syncthreads();

    const int nk = Kd / BK;
    for (int i = 0; i < nk; i++) {
        if (i + 1 < nk) ld((i + 1) * BK, (i + 1) & 1);
        const unsigned tb = sbase + (unsigned)((i & 1) * 2 * TILEH) * 2;
#pragma unroll
        for (int k16 = 0; k16 < BK; k16 += 16) {
            unsigned af[4][4], bf[4][2];
#pragma unroll
            for (int mt = 0; mt < 4; mt++) {
                unsigned a = tb + ((unsigned)(wm + mt * 16 + frow) * BKH + k16 + fcol) * 2;
                ldm4(af[mt], a);
            }
#pragma unroll
            for (int np = 0; np < 2; np++) {
                unsigned a = tb + (unsigned)TILEH * 2 +
                             ((unsigned)(wn + np * 16 + frow) * BKH + k16 + fcol) * 2;
                unsigned r[4];
                ldm4(r, a);
                bf[2 * np + 0][0] = r[0]; bf[2 * np + 1][0] = r[1];
                bf[2 * np + 0][1] = r[2]; bf[2 * np + 1][1] = r[3];
            }
#pragma unroll
            for (int mt = 0; mt < 4; mt++)
#pragma unroll
                for (int nt = 0; nt < 4; nt++)
                    mma16(acc[mt][nt], af[mt], bf[nt][0], bf[nt][1]);
        }
        __syncthreads();
    }

    if (!Ct) {
#pragma unroll
        for (int mt = 0; mt < 4; mt++) {
            const size_t r = m0 + wm + mt * 16 + gr;
            float* cp0 = C + r * (size_t)Nld;
            float* cp1 = C + (r + 8) * (size_t)Nld;
#pragma unroll
            for (int nt = 0; nt < 4; nt++) {
                const int c = n0 + wn + nt * 8 + 2 * gc;
                float b0 = bias ? bias[c] : 0.f;
                float b1 = bias ? bias[c + 1] : 0.f;
                *(float2*)(cp0 + c) = make_float2(acc[mt][nt][0] + b0, acc[mt][nt][1] + b1);
                *(float2*)(cp1 + c) = make_float2(acc[mt][nt][2] + b0, acc[mt][nt][3] + b1);
            }
        }
    } else {
        float* st32 = (float*)smh;   // [128][132]
        __syncthreads();
#pragma unroll
        for (int mt = 0; mt < 4; mt++) {
            const int r0 = wm + mt * 16 + gr;
#pragma unroll
            for (int nt = 0; nt < 4; nt++) {
                const int c = wn + nt * 8 + 2 * gc;
                float b0 = bias ? bias[n0 + c] : 0.f;
                float b1 = bias ? bias[n0 + c + 1] : 0.f;
                st32[r0 * 132 + c] = acc[mt][nt][0] + b0;
                st32[r0 * 132 + c + 1] = acc[mt][nt][1] + b1;
                st32[(r0 + 8) * 132 + c] = acc[mt][nt][2] + b0;
                st32[(r0 + 8) * 132 + c + 1] = acc[mt][nt][3] + b1;
            }
        }
        __syncthreads();
#pragma unroll
        for (int i = 0; i < 16; i++) {
            const int c = wid * 16 + i;
            float4 o;
            o.x = st32[(lane * 4 + 0) * 132 + c];
            o.y = st32[(lane * 4 + 1) * 132 + c];
            o.z = st32[(lane * 4 + 2) * 132 + c];
            o.w = st32[(lane * 4 + 3) * 132 + c];
            *(float4*)(Ct + (size_t)(n0 + c) * CtStride + lane * 4) = o;
        }
        __syncthreads();
    }
}

__global__ __launch_bounds__(256) void k_qkv16(const float* __restrict__ z,
                                               const float* __restrict__ W0,
                                               const float* __restrict__ W1,
                                               const float* __restrict__ W2,
                                               const float* __restrict__ b0,
                                               const float* __restrict__ b1,
                                               const float* __restrict__ b2)
{
    const int zz = blockIdx.z;
    const float* W = (zz == 0) ? W0 : (zz == 1) ? W1 : W2;
    const float* bb = (zz == 0) ? b0 : (zz == 1) ? b1 : b2;
    if (zz == 0) {
        tc16_body(z, W, bb, g_q, ND, ND, ND, blockIdx.x, blockIdx.y, nullptr, 0);
    } else {
        const int b = blockIdx.x >> 4;
        const int mloc = (blockIdx.x & 15) * BM;
        float* base = ((zz == 1) ? g_kt : g_vt) + (size_t)b * ND * NM + mloc;
        tc16_body(z, W, bb, nullptr, 0, ND, ND, blockIdx.x, blockIdx.y, base, NM);
    }
}

// proj split-K x4: z = gemm*4 + split; gemm 0,1 = Ek@kt[b]^T, 2,3 = Ev@vt[b]^T
__global__ __launch_bounds__(256) void k_proj16s(const float* __restrict__ Ek,
                                                 const float* __restrict__ Ev)
{
    const int bz = blockIdx.z;
    const int zz = bz >> 2, sp = bz & 3;
    const int koff = sp * 512;
    const float* A = ((zz < 2) ? Ek : Ev) + koff;
    const float* Bm = (((zz < 2) ? g_kt : g_vt) + (size_t)(zz & 1) * ND * NM) + koff;
    float* C = g_pp + (size_t)bz * (NK * ND);
    tc16_body(A, Bm, nullptr, C, ND, 512, NM, blockIdx.x, blockIdx.y, nullptr, 0);
}

// reduce: K-proj -> g_kp normal; V-proj -> g_vpt transposed [b][d][k]
__global__ __launch_bounds__(256) void k_projred()
{
    const size_t i = (size_t)blockIdx.x * 256 + threadIdx.x;   // over 4*NK*ND
    const int zz = (int)(i / (NK * ND));
    const size_t r = i - (size_t)zz * (NK * ND);
    const size_t base = (size_t)(zz * 4) * (NK * ND) + r;
    float s = g_pp[base] + g_pp[base + (size_t)NK * ND] +
              g_pp[base + 2 * (size_t)NK * ND] + g_pp[base + 3 * (size_t)NK * ND];
    if (zz < 2) {
        g_kp[(size_t)zz * NK * ND + r] = s;
    } else {
        const int b = zz - 2;
        const int k = (int)(r / ND), d = (int)(r - (size_t)k * ND);
        g_vpt[(size_t)b * ND * NK + (size_t)d * NK + k] = s;
    }
}

__global__ __launch_bounds__(256) void k_out16(const float* __restrict__ Wo,
                                               const float* __restrict__ bo,
                                               float* __restrict__ out)
{
    tc16_body(g_o, Wo, bo, out, ND, ND, ND, blockIdx.x, blockIdx.y, nullptr, 0);
}

// ---------------------------------------------------------------------------
// k_cvt: Ek fp32 -> fp16 table (once)
// ---------------------------------------------------------------------------
__global__ __launch_bounds__(256) void k_cvt(const float* __restrict__ Ek)
{
    const int i = blockIdx.x * 256 + threadIdx.x;   // over NK*NS/2
    float2 v = *(const float2*)(Ek + 2 * (size_t)i);
    *(unsigned*)(g_ek16 + 2 * (size_t)i) = pack2(v.x, v.y);
}

// ---------------------------------------------------------------------------
// k_bias256 (256 threads): 128x256 tile, BK=32, software-pipelined.
// ---------------------------------------------------------------------------
#define BK2 32
#define BKH2 40                        // padded half stride (80 B)
#define A2T (128 * BKH2)               // 5120 halves per A buffer
#define B2T (256 * BKH2)               // 10240 halves per B buffer
#define SMP2 ((2 * A2T + 2 * B2T) * 2) // 61440 bytes

__global__ __launch_bounds__(256) void k_bias256(const float* __restrict__ geom,
                                                 const float* __restrict__ cont,
                                                 float* __restrict__ sb)
{
    extern __shared__ unsigned short smh[];
    const unsigned sbase = s2u(smh);
    const unsigned bbase = sbase + (unsigned)(2 * A2T) * 2;
    const int tid = threadIdx.x, lane = tid & 31, wid = tid >> 5;
    const size_t m0 = (size_t)blockIdx.x * BM;      // row in flattened [B*H*M]

    const int ar = tid >> 1, ac = (tid & 1) * 16;
    const float* Ag = geom + (m0 + ar) * (size_t)NS + ac;
    const float* Cg = cont + (m0 + ar) * (size_t)NS + ac;
    const unsigned aoff = (unsigned)(ar * BKH2 + ac) * 2;
    const unsigned short* Bg = g_ek16 + (size_t)tid * NS;
    const unsigned boff = (unsigned)(tid * BKH2) * 2;

    float4 sg[4], sc[4];   // A staging (32 regs)

    auto ldgA = [&](int k0) {
#pragma unroll
        for (int j = 0; j < 4; j++) sg[j] = *(const float4*)(Ag + k0 + j * 4);
#pragma unroll
        for (int j = 0; j < 4; j++) sc[j] = *(const float4*)(Cg + k0 + j * 4);
    };
    auto stsA = [&](int buf) {
        unsigned ab = sbase + (unsigned)(buf * A2T) * 2 + aoff;
#pragma unroll
        for (int j = 0; j < 2; j++) {
            unsigned p0 = pack2(sg[2 * j].x + sc[2 * j].x, sg[2 * j].y + sc[2 * j].y);
            unsigned p1 = pack2(sg[2 * j].z + sc[2 * j].z, sg[2 * j].w + sc[2 * j].w);
            unsigned p2 = pack2(sg[2 * j + 1].x + sc[2 * j + 1].x, sg[2 * j + 1].y + sc[2 * j + 1].y);
            unsigned p3 = pack2(sg[2 * j + 1].z + sc[2 * j + 1].z, sg[2 * j + 1].w + sc[2 * j + 1].w);
            asm volatile("st.shared.v4.b32 [%0], {%1,%2,%3,%4};"
                         :: "r"(ab + j * 16), "r"(p0), "r"(p1), "r"(p2), "r"(p3) : "memory");
        }
    };
    auto cpB = [&](int k0, int buf) {
        unsigned bb = bbase + (unsigned)(buf * B2T) * 2 + boff;
#pragma unroll
        for (int j = 0; j < 4; j++)
            cpa16(bb + j * 16, Bg + k0 + j * 8);
    };

    const int wm = (wid >> 2) * 64, wn = (wid & 3) * 64;
    const int gr = lane >> 2, gc = lane & 3;
    const unsigned frow = (unsigned)(lane & 15), fcol = (unsigned)((lane >> 4) * 8);

    float acc[4][8][4];
#pragma unroll
    for (int mt = 0; mt < 4; mt++)
#pragma unroll
        for (int nt = 0; nt < 8; nt++)
#pragma unroll
            for (int e = 0; e < 4; e++) acc[mt][nt][e] = 0.f;

    cpB(0, 0);
    asm volatile("cp.async.commit_group;" ::: "memory");
    ldgA(0);
    stsA(0);
    asm volatile("cp.async.wait_group 0;" ::: "memory");
    __syncthreads();

    const int nk = NS / BK2;   // 64
    for (int i = 0; i < nk; i++) {
        if (i + 1 < nk) {
            ldgA((i + 1) * BK2);
            cpB((i + 1) * BK2, (i + 1) & 1);
            asm volatile("cp.async.commit_group;" ::: "memory");
        }
        const unsigned ta = sbase + (unsigned)((i & 1) * A2T) * 2;
        const unsigned tb = bbase + (unsigned)((i & 1) * B2T) * 2;
#pragma unroll
        for (int k16 = 0; k16 < BK2; k16 += 16) {
            unsigned af[4][4], bf[8][2];
#pragma unroll
            for (int mt = 0; mt < 4; mt++) {
                unsigned a = ta + ((unsigned)(wm + mt * 16 + frow) * BKH2 + k16 + fcol) * 2;
                ldm4(af[mt], a);
            }
#pragma unroll
            for (int np = 0; np < 4; np++) {
                unsigned a = tb + ((unsigned)(wn + np * 16 + frow) * BKH2 + k16 + fcol) * 2;
                unsigned r[4];
                ldm4(r, a);
                bf[2 * np + 0][0] = r[0]; bf[2 * np + 1][0] = r[1];
                bf[2 * np + 0][1] = r[2]; bf[2 * np + 1][1] = r[3];
            }
#pragma unroll
            for (int mt = 0; mt < 4; mt++)
#pragma unroll
                for (int nt = 0; nt < 8; nt++)
                    mma16(acc[mt][nt], af[mt], bf[nt][0], bf[nt][1]);
        }
        if (i + 1 < nk) {
            stsA((i + 1) & 1);
            asm volatile("cp.async.wait_group 0;" ::: "memory");
        }
        __syncthreads();
    }

#pragma unroll
    for (int mt = 0; mt < 4; mt++) {
        const size_t r = m0 + wm + mt * 16 + gr;
        float* cp0 = sb + r * (size_t)NK;
        float* cp1 = sb + (r + 8) * (size_t)NK;
#pragma unroll
        for (int nt = 0; nt < 8; nt++) {
            const int c = wn + nt * 8 + 2 * gc;
            *(float2*)(cp0 + c) = make_float2(acc[mt][nt][0], acc[mt][nt][1]);
            *(float2*)(cp1 + c) = make_float2(acc[mt][nt][2], acc[mt][nt][3]);
        }
    }
}

// ---------------------------------------------------------------------------
// attn3: mma attention per (b, h, 64-row m tile). 256 threads = 8 warps.
//   GEMM1 (warps 2m x 4n, tile 32x64): scores = (q/8) @ kp^T + g_sb (from gmem)
//   cross-warp softmax; P (unnorm exp, fp16) overlays q/kp smem
//   GEMM2 (warps 2m x 4n, tile 32x16): out = P @ vpt^T * inv -> g_o
// smem (halves): q @0 (64*72), kp @4608 (256*72), P @0 (64*264 overlays),
//                vpt @23040 (64*264), red floats @39936
// ---------------------------------------------------------------------------
#define A3_Q 0
#define A3_KP 4608
#define A3_PST 264
#define A3_VPT 23040
#define A3_RED 39936
#define A3_SM ((A3_RED + 768) * 2)     // 81408 bytes

__global__ __launch_bounds__(256) void attn3()
{
    extern __shared__ unsigned short smh[];
    const unsigned sbase = s2u(smh);
    const int tid = threadIdx.x, lane = tid & 31, wid = tid >> 5;
    const int m0 = blockIdx.x * 64;
    const int h = blockIdx.y, b = blockIdx.z;

    // ---- load q (scaled), kp, vpt as fp16 ----
    {
        const int qr = tid >> 2, qc = (tid & 3) * 16;
        const float* qg = g_q + (size_t)(b * NM + m0 + qr) * ND + h * NDH + qc;
#pragma unroll
        for (int j = 0; j < 4; j++) {
            float4 v = *(const float4*)(qg + j * 4);
            v.x *= 0.125f; v.y *= 0.125f; v.z *= 0.125f; v.w *= 0.125f;
            unsigned u0 = pack2(v.x, v.y), u1 = pack2(v.z, v.w);
            asm volatile("st.shared.v2.b32 [%0], {%1,%2};"
                         :: "r"(sbase + (unsigned)(A3_Q + qr * BKH + qc + j * 4) * 2),
                            "r"(u0), "r"(u1) : "memory");
        }
        const float* kg = g_kp + (size_t)(b * NK + tid) * ND + h * NDH;
#pragma unroll
        for (int j = 0; j < 16; j++) {
            float4 v = *(const float4*)(kg + j * 4);
            unsigned u0 = pack2(v.x, v.y), u1 = pack2(v.z, v.w);
            asm volatile("st.shared.v2.b32 [%0], {%1,%2};"
                         :: "r"(sbase + (unsigned)(A3_KP + tid * BKH + j * 4) * 2),
                            "r"(u0), "r"(u1) : "memory");
        }
        const int vr = tid >> 2, vc = (tid & 3) * 64;
        const float* vg = g_vpt + (size_t)(b * ND + h * NDH + vr) * NK + vc;
#pragma unroll
        for (int j = 0; j < 16; j++) {
            float4 v = *(const float4*)(vg + j * 4);
            unsigned u0 = pack2(v.x, v.y), u1 = pack2(v.z, v.w);
            asm volatile("st.shared.v2.b32 [%0], {%1,%2};"
                         :: "r"(sbase + (unsigned)(A3_VPT + vr * A3_PST + vc + j * 4) * 2),
                            "r"(u0), "r"(u1) : "memory");
        }
    }
    __syncthreads();

    const int wm1 = (wid >> 2) * 32, wn1 = (wid & 3) * 64;
    const int gr = lane >> 2, gc = lane & 3;
    const int wq = wid & 3;
    const unsigned frow = (unsigned)(lane & 15), fcol = (unsigned)((lane >> 4) * 8);

    // ---- GEMM1: scores = (q/8) @ kp^T  (K = 64) ----
    float acc[2][8][4];
#pragma unroll
    for (int mt = 0; mt < 2; mt++)
#pragma unroll
        for (int nt = 0; nt < 8; nt++)
#pragma unroll
            for (int e = 0; e < 4; e++) acc[mt][nt][e] = 0.f;

#pragma unroll
    for (int k16 = 0; k16 < NDH; k16 += 16) {
        unsigned af[2][4], bf[8][2];
#pragma unroll
        for (int mt = 0; mt < 2; mt++) {
            unsigned a = sbase + (unsigned)(A3_Q + (wm1 + mt * 16 + frow) * BKH + k16 + fcol) * 2;
            ldm4(af[mt], a);
        }
#pragma unroll
        for (int np = 0; np < 4; np++) {
            unsigned a = sbase + (unsigned)(A3_KP + (wn1 + np * 16 + frow) * BKH + k16 + fcol) * 2;
            unsigned r[4];
            ldm4(r, a);
            bf[2 * np + 0][0] = r[0]; bf[2 * np + 1][0] = r[1];
            bf[2 * np + 0][1] = r[2]; bf[2 * np + 1][1] = r[3];
        }
#pragma unroll
        for (int mt = 0; mt < 2; mt++)
#pragma unroll
            for (int nt = 0; nt < 8; nt++)
                mma16(acc[mt][nt], af[mt], bf[nt][0], bf[nt][1]);
    }

    // ---- add bias scores from gmem ----
    const float* sbb = g_sb + ((size_t)((b * NH + h) * NM) + m0) * NK;
#pragma unroll
    for (int mt = 0; mt < 2; mt++)
#pragma unroll
        for (int hf = 0; hf < 2; hf++) {
            const int row = wm1 + mt * 16 + gr + hf * 8;
            const float* p = sbb + (size_t)row * NK + wn1 + 2 * gc;
#pragma unroll
            for (int nt = 0; nt < 8; nt++) {
                float2 v = *(const float2*)(p + nt * 8);
                acc[mt][nt][hf * 2 + 0] += v.x;
                acc[mt][nt][hf * 2 + 1] += v.y;
            }
        }

    // ---- softmax (cross-warp via smem red) ----
    float* red = (float*)(smh + A3_RED);
    float mx[4];
#pragma unroll
    for (int mt = 0; mt < 2; mt++)
#pragma unroll
        for (int hf = 0; hf < 2; hf++) {
            float m = -1e30f;
#pragma unroll
            for (int nt = 0; nt < 8; nt++) {
                m = fmaxf(m, acc[mt][nt][hf * 2 + 0]);
                m = fmaxf(m, acc[mt][nt][hf * 2 + 1]);
            }
            m = fmaxf(m, __shfl_xor_sync(0xffffffffu, m, 1));
            m = fmaxf(m, __shfl_xor_sync(0xffffffffu, m, 2));
            mx[mt * 2 + hf] = m;
        }
    if (gc == 0) {
#pragma unroll
        for (int mt = 0; mt < 2; mt++)
#pragma unroll
            for (int hf = 0; hf < 2; hf++)
                red[(wm1 + mt * 16 + gr + hf * 8) * 4 + wq] = mx[mt * 2 + hf];
    }
    __syncthreads();
#pragma unroll
    for (int mt = 0; mt < 2; mt++)
#pragma unroll
        for (int hf = 0; hf < 2; hf++) {
            int row = wm1 + mt * 16 + gr + hf * 8;
            mx[mt * 2 + hf] = fmaxf(fmaxf(red[row * 4 + 0], red[row * 4 + 1]),
                                    fmaxf(red[row * 4 + 2], red[row * 4 + 3]));
        }
    __syncthreads();

    // exp + direct P store (q/kp smem dead after barrier above) + sum
    float sum[4];
#pragma unroll
    for (int r4 = 0; r4 < 4; r4++) sum[r4] = 0.f;
#pragma unroll
    for (int mt = 0; mt < 2; mt++)
#pragma unroll
        for (int nt = 0; nt < 8; nt++)
#pragma unroll
            for (int hf = 0; hf < 2; hf++) {
                float e0 = __expf(acc[mt][nt][hf * 2 + 0] - mx[mt * 2 + hf]);
                float e1 = __expf(acc[mt][nt][hf * 2 + 1] - mx[mt * 2 + hf]);
                sum[mt * 2 + hf] += e0 + e1;
                int row = wm1 + mt * 16 + gr + hf * 8;
                int col = wn1 + nt * 8 + 2 * gc;
                asm volatile("st.shared.b32 [%0], %1;"
                             :: "r"(sbase + (unsigned)(row * A3_PST + col) * 2),
                                "r"(pack2(e0, e1)) : "memory");
            }
#pragma unroll
    for (int r4 = 0; r4 < 4; r4++) {
        sum[r4] += __shfl_xor_sync(0xffffffffu, sum[r4], 1);
        sum[r4] += __shfl_xor_sync(0xffffffffu, sum[r4], 2);
    }
    if (gc == 0) {
#pragma unroll
        for (int mt = 0; mt < 2; mt++)
#pragma unroll
            for (int hf = 0; hf < 2; hf++)
                red[(wm1 + mt * 16 + gr + hf * 8) * 4 + wq] = sum[mt * 2 + hf];
    }
    __syncthreads();
#pragma unroll
    for (int mt = 0; mt < 2; mt++)
#pragma unroll
        for (int hf = 0; hf < 2; hf++) {
            int row = wm1 + mt * 16 + gr + hf * 8;
            sum[mt * 2 + hf] = red[row * 4 + 0] + red[row * 4 + 1] +
                               red[row * 4 + 2] + red[row * 4 + 3];
        }
    __syncthreads();
    if (gc == 0 && wq == 0) {
#pragma unroll
        for (int mt = 0; mt < 2; mt++)
#pragma unroll
            for (int hf = 0; hf < 2; hf++)
                red[wm1 + mt * 16 + gr + hf * 8] = 1.0f / sum[mt * 2 + hf];
    }
    __syncthreads();

    // ---- GEMM2: out[64,64] = P @ vpt^T  (K = 256) ----
    const int wm2 = (wid >> 2) * 32, wn2 = (wid & 3) * 16;
    float o2[2][2][4];
#pragma unroll
    for (int mt = 0; mt < 2; mt++)
#pragma unroll
        for (int nt = 0; nt < 2; nt++)
#pragma unroll
            for (int e = 0; e < 4; e++) o2[mt][nt][e] = 0.f;
#pragma unroll
    for (int k16 = 0; k16 < NK; k16 += 16) {
        unsigned a2[2][4], b2[2][2];
#pragma unroll
        for (int mt = 0; mt < 2; mt++) {
            unsigned a = sbase + (unsigned)((wm2 + mt * 16 + frow) * A3_PST + k16 + fcol) * 2;
            ldm4(a2[mt], a);
        }
        {
            unsigned a = sbase + (unsigned)(A3_VPT + (wn2 + frow) * A3_PST + k16 + fcol) * 2;
            unsigned r[4];
            ldm4(r, a);
            b2[0][0] = r[0]; b2[1][0] = r[1];
            b2[0][1] = r[2]; b2[1][1] = r[3];
        }
#pragma unroll
        for (int mt = 0; mt < 2; mt++)
#pragma unroll
            for (int nt = 0; nt < 2; nt++)
                mma16(o2[mt][nt], a2[mt], b2[nt][0], b2[nt][1]);
    }
#pragma unroll
    for (int mt = 0; mt < 2; mt++) {
        const int rl = wm2 + mt * 16 + gr;
        const float i0 = red[rl], i1 = red[rl + 8];
        float* p0 = g_o + (size_t)(b * NM + m0 + rl) * ND + h * NDH;
        float* p1 = p0 + (size_t)8 * ND;
#pragma unroll
        for (int nt = 0; nt < 2; nt++) {
            const int c = wn2 + nt * 8 + 2 * gc;
            *(float2*)(p0 + c) = make_float2(o2[mt][nt][0] * i0, o2[mt][nt][1] * i0);
            *(float2*)(p1 + c) = make_float2(o2[mt][nt][2] * i1, o2[mt][nt][3] * i1);
        }
    }
}

// ---------------------------------------------------------------------------
extern "C" void kernel_launch(void* const* d_in, const int* in_sizes, int n_in,
                              void* d_out, int out_size)
{
    (void)out_size;
    const float* zp = nullptr;
    const float* geom = nullptr;
    const float* cont = nullptr;
    const float* W[4] = {nullptr, nullptr, nullptr, nullptr};
    const float* bias[4] = {nullptr, nullptr, nullptr, nullptr};
    const float* E[2] = {nullptr, nullptr};
    int wi = 0, bi = 0, ei = 0;
    for (int i = 0; i < n_in; i++) {
        long sz = (long)in_sizes[i];
        if (sz == (long)NB * NM * ND) {
            if (!zp) zp = (const float*)d_in[i];
        } else if (sz == (long)NB * NH * NM * NS) {
            if (!geom) geom = (const float*)d_in[i];
            else if (!cont) cont = (const float*)d_in[i];
        } else if (sz == (long)ND * ND) {
            if (wi < 4) W[wi++] = (const float*)d_in[i];
        } else if (sz == (long)ND) {
            if (bi < 4) bias[bi++] = (const float*)d_in[i];
        } else if (sz == (long)NK * NS) {
            if (ei < 2) E[ei++] = (const float*)d_in[i];
        }
    }
    float* out = (float*)d_out;

    float* sbp;
    cudaGetSymbolAddress((void**)&sbp, g_sb);

    cudaFuncSetAttribute(k_bias256, cudaFuncAttributeMaxDynamicSharedMemorySize, SMP2);
    cudaFuncSetAttribute(k_qkv16, cudaFuncAttributeMaxDynamicSharedMemorySize, SM16);
    cudaFuncSetAttribute(k_proj16s, cudaFuncAttributeMaxDynamicSharedMemorySize, SM16);
    cudaFuncSetAttribute(k_out16, cudaFuncAttributeMaxDynamicSharedMemorySize, SM16);
    cudaFuncSetAttribute(attn3, cudaFuncAttributeMaxDynamicSharedMemorySize, A3_SM);

    dim3 thr(256);
    // Ek -> fp16 table
    k_cvt<<<NK * NS / 2 / 256, thr>>>(E[0]);
    // bias scores: (geom+cont)[65536,2048] @ Ek^T -> g_sb
    k_bias256<<<dim3(NB * NH * NM / BM), thr, SMP2>>>(geom, cont, sbp);
    // q/k/v projections; k,v written transposed for the proj NT GEMMs
    k_qkv16<<<dim3(NB * NM / BM, ND / BN, 3), thr, SM16>>>(zp, W[0], W[1], W[2],
                                                            bias[0], bias[1], bias[2]);
    // Linformer projections (split-K x4) + reduce (V written transposed)
    k_proj16s<<<dim3(NK / BM, ND / BN, 16), thr, SM16>>>(E[0], E[1]);
    k_projred<<<4 * NK * ND / 256, thr>>>();
    // mma attention
    attn3<<<dim3(NM / 64, NH, NB), thr, A3_SM>>>();
    // output projection
    k_out16<<<dim3(NB * NM / BM, ND / BN), thr, SM16>>>(W[3], bias[3], out);
}